// round 16
// baseline (speedup 1.0000x reference)
#include <cuda_runtime.h>
#include <cuda_bf16.h>
#include <math.h>
#include <stdint.h>

// Problem constants
#define T_      80
#define BS_     8
#define DM_     768
#define H_      4
#define DH_     192
#define FF_     1024
#define L_      4
#define LATENT_ 256
#define ROWS_   (T_ * BS_)      // 640
#define NJF_    150
#define A_      6

#define EPS_ATT 1e-6f
#define EPS_LN  1e-5f

typedef __nv_bfloat16 bf16;

// ---------------------------------------------------------------------------
// Scratch (device globals only; no cudaMalloc anywhere)
// ---------------------------------------------------------------------------
__device__ __align__(16) float g_h [ROWS_ * DM_];
__device__ __align__(16) float g_h1[ROWS_ * DM_];
__device__ __align__(16) float g_q [ROWS_ * DM_];   // fp32 GEMM temp

#define BUF_H   0
#define BUF_H1  1
#define BUF_Q   2

__device__ __forceinline__ float* scratch(int code)
{
    switch (code) {
        case BUF_H:  return g_h;
        case BUF_H1: return g_h1;
        default:     return g_q;
    }
}

// bf16 hi/lo split activations
__device__ __align__(16) bf16 s_h_hi  [ROWS_ * DM_];
__device__ __align__(16) bf16 s_h_lo  [ROWS_ * DM_];
__device__ __align__(16) bf16 s_att_hi[ROWS_ * DM_];
__device__ __align__(16) bf16 s_att_lo[ROWS_ * DM_];
__device__ __align__(16) bf16 s_h1_hi [ROWS_ * DM_];
__device__ __align__(16) bf16 s_h1_lo [ROWS_ * DM_];
__device__ __align__(16) bf16 s_ff_hi [ROWS_ * FF_];
__device__ __align__(16) bf16 s_ff_lo [ROWS_ * FF_];
__device__ __align__(16) bf16 s_q_hi  [ROWS_ * DM_];
__device__ __align__(16) bf16 s_q_lo  [ROWS_ * DM_];
__device__ __align__(16) bf16 s_k_hi  [ROWS_ * DM_];
__device__ __align__(16) bf16 s_k_lo  [ROWS_ * DM_];
__device__ __align__(16) bf16 s_v_hi  [ROWS_ * DM_];
__device__ __align__(16) bf16 s_v_lo  [ROWS_ * DM_];

#define SPL_H   0
#define SPL_ATT 1
#define SPL_H1  2
#define SPL_FF  3

__device__ __forceinline__ const bf16* split_hi(int c)
{
    switch (c) { case SPL_H: return s_h_hi; case SPL_ATT: return s_att_hi;
                 case SPL_H1: return s_h1_hi; default: return s_ff_hi; }
}
__device__ __forceinline__ const bf16* split_lo(int c)
{
    switch (c) { case SPL_H: return s_h_lo; case SPL_ATT: return s_att_lo;
                 case SPL_H1: return s_h1_lo; default: return s_ff_lo; }
}
__device__ __forceinline__ bf16* split_hi_w(int c)
{
    switch (c) { case SPL_H: return s_h_hi; case SPL_ATT: return s_att_hi;
                 case SPL_H1: return s_h1_hi; default: return s_ff_hi; }
}
__device__ __forceinline__ bf16* split_lo_w(int c)
{
    switch (c) { case SPL_H: return s_h_lo; case SPL_ATT: return s_att_lo;
                 case SPL_H1: return s_h1_lo; default: return s_ff_lo; }
}

__device__ __forceinline__ void split_store(float v, bf16* hi, bf16* lo, size_t idx)
{
    bf16 h = __float2bfloat16_rn(v);
    hi[idx] = h;
    lo[idx] = __float2bfloat16_rn(v - __bfloat162float(h));
}

// bf16 hi/lo split weights
#define SZW_ATT (L_ * DM_ * DM_)
#define SZW_FF  (L_ * DM_ * FF_)
#define OFF_WQ  ((size_t)0)
#define OFF_WK  ((size_t)SZW_ATT)
#define OFF_WV  ((size_t)(2 * SZW_ATT))
#define OFF_WO  ((size_t)(3 * SZW_ATT))
#define OFF_W1  ((size_t)(4 * SZW_ATT))
#define OFF_W2  ((size_t)(4 * SZW_ATT) + SZW_FF)
#define TOTALW  ((size_t)(4 * SZW_ATT) + 2 * (size_t)SZW_FF)

__device__ __align__(16) bf16 s_W_hi[TOTALW];
__device__ __align__(16) bf16 s_W_lo[TOTALW];

// ---------------------------------------------------------------------------
// Weight splitter (row-major, same layout as GEMM B operand)
// ---------------------------------------------------------------------------
__global__ void split_weights_kernel(const float* __restrict__ Wq, const float* __restrict__ Wk,
                                     const float* __restrict__ Wv, const float* __restrict__ Wo,
                                     const float* __restrict__ W1, const float* __restrict__ W2)
{
    size_t i4 = ((size_t)blockIdx.x * blockDim.x + threadIdx.x) * 4;
    if (i4 >= TOTALW) return;

    const float* src;
    size_t rel;
    if (i4 < OFF_W1) {
        size_t seg = i4 / (size_t)SZW_ATT;
        rel = i4 - seg * (size_t)SZW_ATT;
        src = (seg == 0) ? Wq : (seg == 1) ? Wk : (seg == 2) ? Wv : Wo;
    } else if (i4 < OFF_W2) {
        src = W1; rel = i4 - OFF_W1;
    } else {
        src = W2; rel = i4 - OFF_W2;
    }

    float4 x = *(const float4*)(src + rel);
    const float xs[4] = {x.x, x.y, x.z, x.w};
    #pragma unroll
    for (int j = 0; j < 4; j++)
        split_store(xs[j], s_W_hi, s_W_lo, i4 + j);
}

// ---------------------------------------------------------------------------
// h0
// ---------------------------------------------------------------------------
__global__ void build_h0_kernel(const float* __restrict__ x,
                                const int*   __restrict__ y,
                                const int*   __restrict__ ind_map,
                                const float* __restrict__ skW,
                                const float* __restrict__ skb,
                                const float* __restrict__ muQ,
                                const float* __restrict__ sgQ)
{
    const int r = blockIdx.x;
    const int t = r / BS_;
    const int b = r - t * BS_;
    const int tid = threadIdx.x;

    __shared__ float xrow[NJF_];
    if (tid < NJF_) xrow[tid] = x[(size_t)b * NJF_ * T_ + tid * T_ + t];
    __syncthreads();

    const int a   = ind_map[t * BS_ + b];
    const int cls = y[b * A_ + a];
    const int start = (t == 0) ? 0 : (t + 2);

    const float div = expf(-(logf(10000.0f) / (float)LATENT_) * (float)(tid & ~1));
    const bool  odd = (tid & 1);

    float base0 = muQ[cls * LATENT_ + tid];
    float base1 = sgQ[cls * LATENT_ + tid];
    float acc = skb[tid];
    #pragma unroll 5
    for (int jf = 0; jf < NJF_; jf++) acc += xrow[jf] * skW[jf * LATENT_ + tid];

    const size_t base = (size_t)r * DM_;
    float v0, v1, v2;
    { float ang = (float)(start + 0) * div; v0 = base0 + (odd ? cosf(ang) : sinf(ang)); }
    { float ang = (float)(start + 1) * div; v1 = base1 + (odd ? cosf(ang) : sinf(ang)); }
    { float ang = (float)(start + 2) * div; v2 = acc   + (odd ? cosf(ang) : sinf(ang)); }

    g_h[base + tid]             = v0;
    g_h[base + tid + LATENT_]   = v1;
    g_h[base + tid + 2*LATENT_] = v2;
    split_store(v0, s_h_hi, s_h_lo, base + tid);
    split_store(v1, s_h_hi, s_h_lo, base + tid + LATENT_);
    split_store(v2, s_h_hi, s_h_lo, base + tid + 2*LATENT_);
}

// ---------------------------------------------------------------------------
// bf16 2-term split tensor-core GEMM (m16n8k16 + ldmatrix)
// CTA tile 64x64, BK=32, 8 warps: 2(m) x 2(n) x 2(k-split); warp tile 32x32.
// ---------------------------------------------------------------------------
#define CTM 64
#define CTN 64
#define CTK 32
#define LDA_ 40
#define LDB_ 72

__device__ __forceinline__ uint32_t smem_u32(const void* p)
{
    return (uint32_t)__cvta_generic_to_shared(p);
}

__device__ __forceinline__ void ldm_x4(uint32_t* r, uint32_t addr)
{
    asm volatile("ldmatrix.sync.aligned.m8n8.x4.shared.b16 {%0,%1,%2,%3}, [%4];"
                 : "=r"(r[0]), "=r"(r[1]), "=r"(r[2]), "=r"(r[3]) : "r"(addr));
}
__device__ __forceinline__ void ldm_x4_t(uint32_t* r, uint32_t addr)
{
    asm volatile("ldmatrix.sync.aligned.m8n8.x4.trans.shared.b16 {%0,%1,%2,%3}, [%4];"
                 : "=r"(r[0]), "=r"(r[1]), "=r"(r[2]), "=r"(r[3]) : "r"(addr));
}
__device__ __forceinline__ void mma_bf16(float4& c, const uint32_t* a, uint32_t b0, uint32_t b1)
{
    asm volatile(
        "mma.sync.aligned.m16n8k16.row.col.f32.bf16.bf16.f32 "
        "{%0,%1,%2,%3},{%4,%5,%6,%7},{%8,%9},{%0,%1,%2,%3};"
        : "+f"(c.x), "+f"(c.y), "+f"(c.z), "+f"(c.w)
        : "r"(a[0]), "r"(a[1]), "r"(a[2]), "r"(a[3]), "r"(b0), "r"(b1));
}

// smem pool element offsets (bf16 units)
#define SA_ELEMS (CTM * LDA_)            // 2560
#define SB_ELEMS (CTK * LDB_)            // 2304
#define SA_OFF(buf, pl) (((buf) * 2 + (pl)) * SA_ELEMS)
#define SB_OFF(buf, pl) (10240 + ((buf) * 2 + (pl)) * SB_ELEMS)
#define POOL_ELEMS (10240 + 4 * SB_ELEMS)   // 19456 elems = 38912 B

__device__ __forceinline__ void gemm_bf16_core(
    const bf16* __restrict__ Ahi, const bf16* __restrict__ Alo,
    const bf16* __restrict__ Bhi, const bf16* __restrict__ Blo,
    const float* __restrict__ bias,
    float* Cf32, bf16* Shi, bf16* Slo,
    int N, int K, int rowBase, int colBase, int act, int outmode)
{
    __shared__ __align__(16) bf16 pool[POOL_ELEMS];
    float* red = reinterpret_cast<float*>(pool);   // aliased: used only after mainloop

    const int tid  = threadIdx.x;
    const int lane = tid & 31;
    const int wid  = tid >> 5;
    const int warp_m = wid & 1;
    const int warp_n = (wid >> 1) & 1;
    const int warp_k = wid >> 2;

    // gmem->smem writer coords: A 64rows x 4 col-chunks x 2 planes (512 uint4)
    int apl[2], arj[2], acj[2];
    int bpl[2], brj[2], bcj[2];
    #pragma unroll
    for (int j = 0; j < 2; j++) {
        int i = tid + j * 256;
        apl[j] = i >> 8;            // plane
        int rem = i & 255;
        arj[j] = rem >> 2;          // 0..63
        acj[j] = rem & 3;           // col chunk (x8)
        bpl[j] = i >> 8;
        brj[j] = rem >> 3;          // 0..31 (k)
        bcj[j] = rem & 7;           // col chunk (x8)
    }

    const bf16* Agm[2], * Bgm[2];
    #pragma unroll
    for (int j = 0; j < 2; j++) {
        Agm[j] = (apl[j] ? Alo : Ahi) + (size_t)(rowBase + arj[j]) * K + acj[j] * 8;
        Bgm[j] = (bpl[j] ? Blo : Bhi) + (size_t)brj[j] * N + colBase + bcj[j] * 8;
    }

    // ldmatrix offsets
    const int aoff0 = (warp_m * 32 + (lane & 15)) * LDA_ + warp_k * 16 + ((lane >> 4) << 3);
    const int aoff1 = aoff0 + 16 * LDA_;
    const int boff0 = (warp_k * 16 + (lane & 15)) * LDB_ + warp_n * 32 + ((lane >> 4) << 3);
    const int boff1 = boff0 + 16;

    float4 acc[2][4];
    #pragma unroll
    for (int mi = 0; mi < 2; mi++)
        #pragma unroll
        for (int nt = 0; nt < 4; nt++)
            acc[mi][nt] = make_float4(0.f, 0.f, 0.f, 0.f);

    const int KT = K / CTK;

    // preload tile 0
    #pragma unroll
    for (int j = 0; j < 2; j++) {
        *(uint4*)&pool[SA_OFF(0, apl[j]) + arj[j] * LDA_ + acj[j] * 8] = *(const uint4*)Agm[j];
        *(uint4*)&pool[SB_OFF(0, bpl[j]) + brj[j] * LDB_ + bcj[j] * 8] = *(const uint4*)Bgm[j];
    }
    __syncthreads();

    int buf = 0;
    for (int kt = 0; kt < KT; kt++) {
        uint4 pa[2], pb[2];
        const bool more = (kt + 1 < KT);
        if (more) {
            #pragma unroll
            for (int j = 0; j < 2; j++) {
                pa[j] = *(const uint4*)(Agm[j] + (kt + 1) * CTK);
                pb[j] = *(const uint4*)(Bgm[j] + (size_t)(kt + 1) * CTK * N);
            }
        }

        uint32_t ah0[4], ah1[4], al0[4], al1[4], bh0[4], bh1[4], bl0[4], bl1[4];
        ldm_x4  (ah0, smem_u32(&pool[SA_OFF(buf, 0) + aoff0]));
        ldm_x4  (ah1, smem_u32(&pool[SA_OFF(buf, 0) + aoff1]));
        ldm_x4  (al0, smem_u32(&pool[SA_OFF(buf, 1) + aoff0]));
        ldm_x4  (al1, smem_u32(&pool[SA_OFF(buf, 1) + aoff1]));
        ldm_x4_t(bh0, smem_u32(&pool[SB_OFF(buf, 0) + boff0]));
        ldm_x4_t(bh1, smem_u32(&pool[SB_OFF(buf, 0) + boff1]));
        ldm_x4_t(bl0, smem_u32(&pool[SB_OFF(buf, 1) + boff0]));
        ldm_x4_t(bl1, smem_u32(&pool[SB_OFF(buf, 1) + boff1]));

        // mi = 0
        mma_bf16(acc[0][0], ah0, bh0[0], bh0[1]);
        mma_bf16(acc[0][0], ah0, bl0[0], bl0[1]);
        mma_bf16(acc[0][0], al0, bh0[0], bh0[1]);
        mma_bf16(acc[0][1], ah0, bh0[2], bh0[3]);
        mma_bf16(acc[0][1], ah0, bl0[2], bl0[3]);
        mma_bf16(acc[0][1], al0, bh0[2], bh0[3]);
        mma_bf16(acc[0][2], ah0, bh1[0], bh1[1]);
        mma_bf16(acc[0][2], ah0, bl1[0], bl1[1]);
        mma_bf16(acc[0][2], al0, bh1[0], bh1[1]);
        mma_bf16(acc[0][3], ah0, bh1[2], bh1[3]);
        mma_bf16(acc[0][3], ah0, bl1[2], bl1[3]);
        mma_bf16(acc[0][3], al0, bh1[2], bh1[3]);
        // mi = 1
        mma_bf16(acc[1][0], ah1, bh0[0], bh0[1]);
        mma_bf16(acc[1][0], ah1, bl0[0], bl0[1]);
        mma_bf16(acc[1][0], al1, bh0[0], bh0[1]);
        mma_bf16(acc[1][1], ah1, bh0[2], bh0[3]);
        mma_bf16(acc[1][1], ah1, bl0[2], bl0[3]);
        mma_bf16(acc[1][1], al1, bh0[2], bh0[3]);
        mma_bf16(acc[1][2], ah1, bh1[0], bh1[1]);
        mma_bf16(acc[1][2], ah1, bl1[0], bl1[1]);
        mma_bf16(acc[1][2], al1, bh1[0], bh1[1]);
        mma_bf16(acc[1][3], ah1, bh1[2], bh1[3]);
        mma_bf16(acc[1][3], ah1, bl1[2], bl1[3]);
        mma_bf16(acc[1][3], al1, bh1[2], bh1[3]);

        if (more) {
            const int nb = buf ^ 1;
            #pragma unroll
            for (int j = 0; j < 2; j++) {
                *(uint4*)&pool[SA_OFF(nb, apl[j]) + arj[j] * LDA_ + acj[j] * 8] = pa[j];
                *(uint4*)&pool[SB_OFF(nb, bpl[j]) + brj[j] * LDB_ + bcj[j] * 8] = pb[j];
            }
        }
        __syncthreads();
        buf ^= 1;
    }

    // k-split reduction through (aliased) smem
    float* af = reinterpret_cast<float*>(acc);
    if (warp_k == 1) {
        int base = (wid - 4) * 32 + lane;
        #pragma unroll
        for (int j = 0; j < 32; j++) red[j * 128 + base] = af[j];
    }
    __syncthreads();
    if (warp_k == 0) {
        int base = wid * 32 + lane;
        #pragma unroll
        for (int j = 0; j < 32; j++) af[j] += red[j * 128 + base];

        #pragma unroll
        for (int mi = 0; mi < 2; mi++) {
            const int row0 = rowBase + warp_m * 32 + mi * 16 + (lane >> 2);
            #pragma unroll
            for (int nt = 0; nt < 4; nt++) {
                const int col = colBase + warp_n * 32 + nt * 8 + 2 * (lane & 3);
                float2 bb = *(const float2*)(bias + col);
                float v00 = acc[mi][nt].x + bb.x, v01 = acc[mi][nt].y + bb.y;
                float v10 = acc[mi][nt].z + bb.x, v11 = acc[mi][nt].w + bb.y;
                if (act == 1) {
                    v00 = (v00 > 0.f) ? (v00 + 1.f) : expf(v00);
                    v01 = (v01 > 0.f) ? (v01 + 1.f) : expf(v01);
                    v10 = (v10 > 0.f) ? (v10 + 1.f) : expf(v10);
                    v11 = (v11 > 0.f) ? (v11 + 1.f) : expf(v11);
                } else if (act == 2) {
                    v00 = fmaxf(v00, 0.f); v01 = fmaxf(v01, 0.f);
                    v10 = fmaxf(v10, 0.f); v11 = fmaxf(v11, 0.f);
                }
                if (outmode & 1) {
                    *(float2*)(Cf32 + (size_t)row0 * N + col)       = make_float2(v00, v01);
                    *(float2*)(Cf32 + (size_t)(row0 + 8) * N + col) = make_float2(v10, v11);
                }
                if (outmode & 2) {
                    split_store(v00, Shi, Slo, (size_t)row0 * N + col);
                    split_store(v01, Shi, Slo, (size_t)row0 * N + col + 1);
                    split_store(v10, Shi, Slo, (size_t)(row0 + 8) * N + col);
                    split_store(v11, Shi, Slo, (size_t)(row0 + 8) * N + col + 1);
                }
            }
        }
    }
}

__global__ void __launch_bounds__(256) gemm_bf16_kernel(
    int a_code, size_t w_off, const float* __restrict__ bias,
    int N, int K, int act, int outmode, int c_code, int s_code)
{
    float* Cf32 = (outmode & 1) ? scratch(c_code) : nullptr;
    bf16* Shi = (outmode & 2) ? split_hi_w(s_code) : nullptr;
    bf16* Slo = (outmode & 2) ? split_lo_w(s_code) : nullptr;
    gemm_bf16_core(split_hi(a_code), split_lo(a_code),
                   s_W_hi + w_off, s_W_lo + w_off, bias,
                   Cf32, Shi, Slo, N, K,
                   blockIdx.y * CTM, blockIdx.x * CTN, act, outmode);
}

__global__ void __launch_bounds__(256) gemm_qkv_bf16_kernel(
    size_t offq, size_t offk, size_t offv,
    const float* __restrict__ bq,
    const float* __restrict__ bk,
    const float* __restrict__ bv)
{
    const int gcol = blockIdx.x * CTN;
    const int mat  = gcol / DM_;
    const int colBase = gcol - mat * DM_;
    size_t w_off      = (mat == 0) ? offq : (mat == 1) ? offk : offv;
    const float* bias = (mat == 0) ? bq   : (mat == 1) ? bk   : bv;
    bf16* shi         = (mat == 0) ? s_q_hi : (mat == 1) ? s_k_hi : s_v_hi;
    bf16* slo         = (mat == 0) ? s_q_lo : (mat == 1) ? s_k_lo : s_v_lo;
    const int act     = (mat < 2) ? 1 : 0;
    gemm_bf16_core(s_h_hi, s_h_lo, s_W_hi + w_off, s_W_lo + w_off, nullptr ? nullptr : bias,
                   nullptr, shi, slo, DM_, DM_,
                   blockIdx.y * CTM, colBase, act, 2);
}

// ---------------------------------------------------------------------------
// Tensor-core causal linear attention (R13-validated, unchanged)
// ---------------------------------------------------------------------------
#define SLD 88
#define QP  200
#define KP  40

__device__ __forceinline__ void split2smem(float v, bf16* hi, bf16* lo, int idx)
{
    bf16 h = __float2bfloat16_rn(v);
    hi[idx] = h;
    lo[idx] = __float2bfloat16_rn(v - __bfloat162float(h));
}

__global__ void attn_mma_kernel()
{
    __shared__ __align__(16) bf16 apool[19200];
    __shared__ __align__(16) bf16 sSh[16 * SLD];
    __shared__ __align__(16) bf16 sSl[16 * SLD];
    __shared__ float inv_s[16];

    const int mc = blockIdx.x;
    const int bh = blockIdx.y;
    const int b = bh >> 2, h = bh & 3;
    const int t0 = mc * 16;
    const int W  = (mc + 1) * 16;
    const int tid = threadIdx.x, lane = tid & 31, wid = tid >> 5;
    const int g = lane >> 2, tq = lane & 3;

    const size_t rowB = (size_t)b * DM_ + h * DH_;

    float4 accA[2] = {{0,0,0,0},{0,0,0,0}};

    for (int i = tid; i < 768; i += 256) {
        int p = i / 384, rem = i - p * 384;
        int row = rem / 24, c8 = rem - row * 24;
        const bf16* src = p ? s_q_lo : s_q_hi;
        *(uint4*)&apool[12800 + p * 3200 + row * QP + c8 * 8] =
            *(const uint4*)&src[(size_t)(t0 + row) * BS_ * DM_ + rowB + c8 * 8];
    }
    {
        const int nld = W * 8;
        for (int i = tid; i < nld; i += 256) {
            int p = i / (W * 4), rem = i - p * (W * 4);
            int row = rem >> 2, c4 = rem & 3;
            const bf16* src = p ? s_k_lo : s_k_hi;
            *(uint4*)&apool[p * 3200 + row * KP + c4 * 8] =
                *(const uint4*)&src[(size_t)row * BS_ * DM_ + rowB + c4 * 8];
        }
    }
    __syncthreads();

    int buf = 0;
    for (int kc = 0; kc < 6; kc++) {
        if (wid <= mc) {
            #pragma unroll
            for (int x = 0; x < 2; x++) {
                uint32_t qh[4], ql[4], kh[4], kl[4];
                int qoff = (lane & 15) * QP + kc * 32 + x * 16 + ((lane >> 4) << 3);
                int koff = (wid * 16 + (lane & 15)) * KP + x * 16 + ((lane >> 4) << 3);
                ldm_x4(qh, smem_u32(&apool[12800 + qoff]));
                ldm_x4(ql, smem_u32(&apool[16000 + qoff]));
                ldm_x4(kh, smem_u32(&apool[(buf * 2) * 3200 + koff]));
                ldm_x4(kl, smem_u32(&apool[(buf * 2 + 1) * 3200 + koff]));
                mma_bf16(accA[0], qh, kh[0], kh[2]);
                mma_bf16(accA[0], qh, kl[0], kl[2]);
                mma_bf16(accA[0], ql, kh[0], kh[2]);
                mma_bf16(accA[1], qh, kh[1], kh[3]);
                mma_bf16(accA[1], qh, kl[1], kl[3]);
                mma_bf16(accA[1], ql, kh[1], kh[3]);
            }
        }
        if (kc < 5) {
            const int nld = W * 8;
            const int cbase = (kc + 1) * 32;
            for (int i = tid; i < nld; i += 256) {
                int p = i / (W * 4), rem = i - p * (W * 4);
                int row = rem >> 2, c4 = rem & 3;
                const bf16* src = p ? s_k_lo : s_k_hi;
                *(uint4*)&apool[((buf ^ 1) * 2 + p) * 3200 + row * KP + c4 * 8] =
                    *(const uint4*)&src[(size_t)row * BS_ * DM_ + rowB + cbase + c4 * 8];
            }
        }
        __syncthreads();
        buf ^= 1;
    }

    if (wid <= mc) {
        int r0 = g, r1 = g + 8;
        #pragma unroll
        for (int n8 = 0; n8 < 2; n8++) {
            int c = wid * 16 + n8 * 8 + 2 * tq;
            float4 a = accA[n8];
            split2smem((c     <= t0 + r0) ? a.x : 0.f, sSh, sSl, r0 * SLD + c);
            split2smem((c + 1 <= t0 + r0) ? a.y : 0.f, sSh, sSl, r0 * SLD + c + 1);
            split2smem((c     <= t0 + r1) ? a.z : 0.f, sSh, sSl, r1 * SLD + c);
            split2smem((c + 1 <= t0 + r1) ? a.w : 0.f, sSh, sSl, r1 * SLD + c + 1);
        }
    }
    __syncthreads();

    for (int i = tid; i < 768; i += 256) {
        int p = i / 384, rem = i - p * 384;
        int row = rem / 24, c8 = rem - row * 24;
        const bf16* src = p ? s_v_lo : s_v_hi;
        *(uint4*)&apool[p * 3200 + row * QP + c8 * 8] =
            *(const uint4*)&src[(size_t)row * BS_ * DM_ + rowB + c8 * 8];
    }
    if (tid < 16) {
        float s = 0.0f;
        for (int c = 0; c < W; c++)
            s += __bfloat162float(sSh[tid * SLD + c]) + __bfloat162float(sSl[tid * SLD + c]);
        inv_s[tid] = 1.0f / (s + EPS_ATT);
    }
    __syncthreads();

    float4 accC[2][2];
    #pragma unroll
    for (int j = 0; j < 2; j++) { accC[j][0] = make_float4(0,0,0,0); accC[j][1] = make_float4(0,0,0,0); }

    buf = 0;
    for (int vc = 0; vc <= mc; vc++) {
        uint32_t sh[4], sl[4];
        int aoff = (lane & 15) * SLD + vc * 16 + ((lane >> 4) << 3);
        ldm_x4(sh, smem_u32(&sSh[aoff]));
        ldm_x4(sl, smem_u32(&sSl[aoff]));

        #pragma unroll
        for (int j = 0; j < 2; j++) {
            int ni = wid + 8 * j;
            if (ni < 12) {
                uint32_t vh[4], vl[4];
                int boff = (lane & 15) * QP + ni * 16 + ((lane >> 4) << 3);
                ldm_x4_t(vh, smem_u32(&apool[(buf * 2) * 3200 + boff]));
                ldm_x4_t(vl, smem_u32(&apool[(buf * 2 + 1) * 3200 + boff]));
                mma_bf16(accC[j][0], sh, vh[0], vh[1]);
                mma_bf16(accC[j][0], sh, vl[0], vl[1]);
                mma_bf16(accC[j][0], sl, vh[0], vh[1]);
                mma_bf16(accC[j][1], sh, vh[2], vh[3]);
                mma_bf16(accC[j][1], sh, vl[2], vl[3]);
                mma_bf16(accC[j][1], sl, vh[2], vh[3]);
            }
        }

        if (vc < mc) {
            const int rbase = (vc + 1) * 16;
            for (int i = tid; i < 768; i += 256) {
                int p = i / 384, rem = i - p * 384;
                int row = rem / 24, c8 = rem - row * 24;
                const bf16* src = p ? s_v_lo : s_v_hi;
                *(uint4*)&apool[((buf ^ 1) * 2 + p) * 3200 + row * QP + c8 * 8] =
                    *(const uint4*)&src[(size_t)(rbase + row) * BS_ * DM_ + rowB + c8 * 8];
            }
        }
        __syncthreads();
        buf ^= 1;
    }

    {
        int r0 = g, r1 = g + 8;
        float i0 = inv_s[r0], i1 = inv_s[r1];
        #pragma unroll
        for (int j = 0; j < 2; j++) {
            int ni = wid + 8 * j;
            if (ni < 12) {
                #pragma unroll
                for (int n8 = 0; n8 < 2; n8++) {
                    int d = ni * 16 + n8 * 8 + 2 * tq;
                    float4 a = accC[j][n8];
                    size_t o0 = (size_t)(t0 + r0) * BS_ * DM_ + rowB + d;
                    size_t o1 = (size_t)(t0 + r1) * BS_ * DM_ + rowB + d;
                    split_store(a.x * i0, s_att_hi, s_att_lo, o0);
                    split_store(a.y * i0, s_att_hi, s_att_lo, o0 + 1);
                    split_store(a.z * i1, s_att_hi, s_att_lo, o1);
                    split_store(a.w * i1, s_att_hi, s_att_lo, o1 + 1);
                }
            }
        }
    }
}

// ---------------------------------------------------------------------------
// LayerNorm
// ---------------------------------------------------------------------------
__device__ __forceinline__ float block_sum_256(float val)
{
    __shared__ float sh[8];
    const int lane = threadIdx.x & 31;
    const int w    = threadIdx.x >> 5;
    #pragma unroll
    for (int o = 16; o > 0; o >>= 1) val += __shfl_down_sync(0xffffffffu, val, o);
    if (lane == 0) sh[w] = val;
    __syncthreads();
    if (w == 0) {
        float r = (lane < 8) ? sh[lane] : 0.0f;
        #pragma unroll
        for (int o = 4; o > 0; o >>= 1) r += __shfl_down_sync(0xffffffffu, r, o);
        if (lane == 0) sh[0] = r;
    }
    __syncthreads();
    float res = sh[0];
    __syncthreads();
    return res;
}

__global__ void ln_residual_kernel(int x_code, int y_code,
                                   const float* __restrict__ g, const float* __restrict__ bt,
                                   int out_code, int s_code)
{
    const float* x  = scratch(x_code);
    const float* yv = scratch(y_code);
    float* out      = scratch(out_code);
    bf16* shi = split_hi_w(s_code);
    bf16* slo = split_lo_w(s_code);

    const int row = blockIdx.x;
    const int tid = threadIdx.x;
    const size_t base = (size_t)row * DM_;

    float v0 = x[base + tid]       + yv[base + tid];
    float v1 = x[base + tid + 256] + yv[base + tid + 256];
    float v2 = x[base + tid + 512] + yv[base + tid + 512];

    float mean = block_sum_256(v0 + v1 + v2) * (1.0f / (float)DM_);
    float d0 = v0 - mean, d1 = v1 - mean, d2 = v2 - mean;
    float var = block_sum_256(d0*d0 + d1*d1 + d2*d2) * (1.0f / (float)DM_);
    float rstd = rsqrtf(var + EPS_LN);

    float o0 = d0 * rstd * g[tid]       + bt[tid];
    float o1 = d1 * rstd * g[tid + 256] + bt[tid + 256];
    float o2 = d2 * rstd * g[tid + 512] + bt[tid + 512];

    out[base + tid]       = o0;
    out[base + tid + 256] = o1;
    out[base + tid + 512] = o2;
    split_store(o0, shi, slo, base + tid);
    split_store(o1, shi, slo, base + tid + 256);
    split_store(o2, shi, slo, base + tid + 512);
}

// ---------------------------------------------------------------------------
// Final gather + LN
// ---------------------------------------------------------------------------
__global__ void gather_kernel(const int* __restrict__ act_ts,
                              const float* __restrict__ g, const float* __restrict__ bt,
                              float* __restrict__ out)
{
    const int ba = blockIdx.x;
    const int b  = ba / A_;
    int t = act_ts[ba] - 1;
    if (t < 0) t = 0;
    const int row = t * BS_ + b;
    const int tid = threadIdx.x;
    const size_t base = (size_t)row * DM_;

    float v0 = g_h[base + tid];
    float v1 = g_h[base + tid + 256];
    float v2 = g_h[base + tid + 512];

    float mean = block_sum_256(v0 + v1 + v2) * (1.0f / (float)DM_);
    float d0 = v0 - mean, d1 = v1 - mean, d2 = v2 - mean;
    float var = block_sum_256(d0*d0 + d1*d1 + d2*d2) * (1.0f / (float)DM_);
    float rstd = rsqrtf(var + EPS_LN);

    out[(size_t)ba * LATENT_ + tid]                      = d0 * rstd * g[tid]       + bt[tid];
    out[(size_t)BS_ * A_ * LATENT_ + ba * LATENT_ + tid] = d1 * rstd * g[tid + 256] + bt[tid + 256];
}

// ---------------------------------------------------------------------------
// Host orchestration: kernel launches ONLY
// ---------------------------------------------------------------------------
extern "C" void kernel_launch(void* const* d_in, const int* in_sizes, int n_in,
                              void* d_out, int out_size)
{
    const float* x    = (const float*)d_in[0];
    const int*   y    = (const int*)  d_in[1];
    const int*   ind  = (const int*)  d_in[2];
    const int*   ats  = (const int*)  d_in[3];
    const float* skW  = (const float*)d_in[4];
    const float* skb  = (const float*)d_in[5];
    const float* muQ  = (const float*)d_in[6];
    const float* sgQ  = (const float*)d_in[7];
    const float* Wq   = (const float*)d_in[8];
    const float* bq   = (const float*)d_in[9];
    const float* Wk   = (const float*)d_in[10];
    const float* bk   = (const float*)d_in[11];
    const float* Wv   = (const float*)d_in[12];
    const float* bv   = (const float*)d_in[13];
    const float* Wo   = (const float*)d_in[14];
    const float* bo   = (const float*)d_in[15];
    const float* W1   = (const float*)d_in[16];
    const float* b1   = (const float*)d_in[17];
    const float* W2   = (const float*)d_in[18];
    const float* b2   = (const float*)d_in[19];
    const float* l1g  = (const float*)d_in[20];
    const float* l1b  = (const float*)d_in[21];
    const float* l2g  = (const float*)d_in[22];
    const float* l2b  = (const float*)d_in[23];
    const float* lfg  = (const float*)d_in[24];
    const float* lfb  = (const float*)d_in[25];
    float* out = (float*)d_out;

    split_weights_kernel<<<(unsigned)((TOTALW / 4 + 255) / 256), 256>>>(Wq, Wk, Wv, Wo, W1, W2);
    build_h0_kernel<<<ROWS_, 256>>>(x, y, ind, skW, skb, muQ, sgQ);

    const dim3 gQKV(3 * DM_ / CTN, ROWS_ / CTM);   // 36 x 10 = 360
    const dim3 g768(DM_ / CTN, ROWS_ / CTM);       // 12 x 10 = 120
    const dim3 g1024(FF_ / CTN, ROWS_ / CTM);      // 16 x 10 = 160
    const dim3 gAttn(5, BS_ * H_);                 // 160 blocks

    const size_t szAttL = (size_t)DM_ * DM_;
    const size_t szFFL  = (size_t)DM_ * FF_;

    for (int l = 0; l < L_; l++) {
        gemm_qkv_bf16_kernel<<<gQKV, 256>>>(OFF_WQ + l * szAttL,
                                            OFF_WK + l * szAttL,
                                            OFF_WV + l * szAttL,
                                            bq + l * DM_, bk + l * DM_, bv + l * DM_);
        attn_mma_kernel<<<gAttn, 256>>>();
        gemm_bf16_kernel<<<g768, 256>>>(SPL_ATT, OFF_WO + l * szAttL, bo + l * DM_,
                                        DM_, DM_, 0, 1, BUF_Q, 0);
        ln_residual_kernel<<<ROWS_, 256>>>(BUF_H, BUF_Q, l1g + l * DM_, l1b + l * DM_,
                                           BUF_H1, SPL_H1);
        gemm_bf16_kernel<<<g1024, 256>>>(SPL_H1, OFF_W1 + l * szFFL, b1 + l * FF_,
                                         FF_, DM_, 2, 2, 0, SPL_FF);
        gemm_bf16_kernel<<<g768, 256>>>(SPL_FF, OFF_W2 + l * szFFL, b2 + l * DM_,
                                        DM_, FF_, 0, 1, BUF_Q, 0);
        ln_residual_kernel<<<ROWS_, 256>>>(BUF_H1, BUF_Q, l2g + l * DM_, l2b + l * DM_,
                                           BUF_H, SPL_H);
    }

    gather_kernel<<<BS_ * A_, 256>>>(ats, lfg, lfb, out);
}

// round 17
// speedup vs baseline: 1.2158x; 1.2158x over previous
#include <cuda_runtime.h>
#include <cuda_bf16.h>
#include <math.h>
#include <stdint.h>

// Problem constants
#define T_      80
#define BS_     8
#define DM_     768
#define H_      4
#define DH_     192
#define FF_     1024
#define L_      4
#define LATENT_ 256
#define ROWS_   (T_ * BS_)      // 640
#define NJF_    150
#define A_      6

#define EPS_ATT 1e-6f
#define EPS_LN  1e-5f

typedef __nv_bfloat16 bf16;

// ---------------------------------------------------------------------------
// Scratch (device globals only; no cudaMalloc anywhere)
// ---------------------------------------------------------------------------
__device__ __align__(16) float g_h [ROWS_ * DM_];
__device__ __align__(16) float g_h1[ROWS_ * DM_];
__device__ __align__(16) float g_q [ROWS_ * DM_];   // fp32 GEMM temp

#define BUF_H   0
#define BUF_H1  1
#define BUF_Q   2

__device__ __forceinline__ float* scratch(int code)
{
    switch (code) {
        case BUF_H:  return g_h;
        case BUF_H1: return g_h1;
        default:     return g_q;
    }
}

// bf16 hi/lo split activations
__device__ __align__(16) bf16 s_h_hi  [ROWS_ * DM_];
__device__ __align__(16) bf16 s_h_lo  [ROWS_ * DM_];
__device__ __align__(16) bf16 s_att_hi[ROWS_ * DM_];
__device__ __align__(16) bf16 s_att_lo[ROWS_ * DM_];
__device__ __align__(16) bf16 s_h1_hi [ROWS_ * DM_];
__device__ __align__(16) bf16 s_h1_lo [ROWS_ * DM_];
__device__ __align__(16) bf16 s_ff_hi [ROWS_ * FF_];
__device__ __align__(16) bf16 s_ff_lo [ROWS_ * FF_];
__device__ __align__(16) bf16 s_q_hi  [ROWS_ * DM_];
__device__ __align__(16) bf16 s_q_lo  [ROWS_ * DM_];
__device__ __align__(16) bf16 s_k_hi  [ROWS_ * DM_];
__device__ __align__(16) bf16 s_k_lo  [ROWS_ * DM_];
__device__ __align__(16) bf16 s_v_hi  [ROWS_ * DM_];
__device__ __align__(16) bf16 s_v_lo  [ROWS_ * DM_];

#define SPL_H   0
#define SPL_ATT 1
#define SPL_H1  2
#define SPL_FF  3

__device__ __forceinline__ const bf16* split_hi(int c)
{
    switch (c) { case SPL_H: return s_h_hi; case SPL_ATT: return s_att_hi;
                 case SPL_H1: return s_h1_hi; default: return s_ff_hi; }
}
__device__ __forceinline__ const bf16* split_lo(int c)
{
    switch (c) { case SPL_H: return s_h_lo; case SPL_ATT: return s_att_lo;
                 case SPL_H1: return s_h1_lo; default: return s_ff_lo; }
}
__device__ __forceinline__ bf16* split_hi_w(int c)
{
    switch (c) { case SPL_H: return s_h_hi; case SPL_ATT: return s_att_hi;
                 case SPL_H1: return s_h1_hi; default: return s_ff_hi; }
}
__device__ __forceinline__ bf16* split_lo_w(int c)
{
    switch (c) { case SPL_H: return s_h_lo; case SPL_ATT: return s_att_lo;
                 case SPL_H1: return s_h1_lo; default: return s_ff_lo; }
}

__device__ __forceinline__ void split_store(float v, bf16* hi, bf16* lo, size_t idx)
{
    bf16 h = __float2bfloat16_rn(v);
    hi[idx] = h;
    lo[idx] = __float2bfloat16_rn(v - __bfloat162float(h));
}

// bf16 hi/lo split weights
#define SZW_ATT (L_ * DM_ * DM_)
#define SZW_FF  (L_ * DM_ * FF_)
#define OFF_WQ  ((size_t)0)
#define OFF_WK  ((size_t)SZW_ATT)
#define OFF_WV  ((size_t)(2 * SZW_ATT))
#define OFF_WO  ((size_t)(3 * SZW_ATT))
#define OFF_W1  ((size_t)(4 * SZW_ATT))
#define OFF_W2  ((size_t)(4 * SZW_ATT) + SZW_FF)
#define TOTALW  ((size_t)(4 * SZW_ATT) + 2 * (size_t)SZW_FF)

__device__ __align__(16) bf16 s_W_hi[TOTALW];
__device__ __align__(16) bf16 s_W_lo[TOTALW];

// ---------------------------------------------------------------------------
// PTX helpers
// ---------------------------------------------------------------------------
__device__ __forceinline__ uint32_t smem_u32(const void* p)
{
    return (uint32_t)__cvta_generic_to_shared(p);
}
__device__ __forceinline__ void cp16(uint32_t smem_dst, const void* gsrc)
{
    asm volatile("cp.async.ca.shared.global [%0], [%1], 16;"
                 :: "r"(smem_dst), "l"(gsrc) : "memory");
}
#define CP_COMMIT() asm volatile("cp.async.commit_group;" ::: "memory")
#define CP_WAIT0()  asm volatile("cp.async.wait_group 0;" ::: "memory")

__device__ __forceinline__ void ldm_x4(uint32_t* r, uint32_t addr)
{
    asm volatile("ldmatrix.sync.aligned.m8n8.x4.shared.b16 {%0,%1,%2,%3}, [%4];"
                 : "=r"(r[0]), "=r"(r[1]), "=r"(r[2]), "=r"(r[3]) : "r"(addr));
}
__device__ __forceinline__ void ldm_x4_t(uint32_t* r, uint32_t addr)
{
    asm volatile("ldmatrix.sync.aligned.m8n8.x4.trans.shared.b16 {%0,%1,%2,%3}, [%4];"
                 : "=r"(r[0]), "=r"(r[1]), "=r"(r[2]), "=r"(r[3]) : "r"(addr));
}
__device__ __forceinline__ void mma_bf16(float4& c, const uint32_t* a, uint32_t b0, uint32_t b1)
{
    asm volatile(
        "mma.sync.aligned.m16n8k16.row.col.f32.bf16.bf16.f32 "
        "{%0,%1,%2,%3},{%4,%5,%6,%7},{%8,%9},{%0,%1,%2,%3};"
        : "+f"(c.x), "+f"(c.y), "+f"(c.z), "+f"(c.w)
        : "r"(a[0]), "r"(a[1]), "r"(a[2]), "r"(a[3]), "r"(b0), "r"(b1));
}

// ---------------------------------------------------------------------------
// Weight splitter
// ---------------------------------------------------------------------------
__global__ void split_weights_kernel(const float* __restrict__ Wq, const float* __restrict__ Wk,
                                     const float* __restrict__ Wv, const float* __restrict__ Wo,
                                     const float* __restrict__ W1, const float* __restrict__ W2)
{
    size_t i4 = ((size_t)blockIdx.x * blockDim.x + threadIdx.x) * 4;
    if (i4 >= TOTALW) return;

    const float* src;
    size_t rel;
    if (i4 < OFF_W1) {
        size_t seg = i4 / (size_t)SZW_ATT;
        rel = i4 - seg * (size_t)SZW_ATT;
        src = (seg == 0) ? Wq : (seg == 1) ? Wk : (seg == 2) ? Wv : Wo;
    } else if (i4 < OFF_W2) {
        src = W1; rel = i4 - OFF_W1;
    } else {
        src = W2; rel = i4 - OFF_W2;
    }

    float4 x = *(const float4*)(src + rel);
    const float xs[4] = {x.x, x.y, x.z, x.w};
    #pragma unroll
    for (int j = 0; j < 4; j++)
        split_store(xs[j], s_W_hi, s_W_lo, i4 + j);
}

// ---------------------------------------------------------------------------
// h0
// ---------------------------------------------------------------------------
__global__ void build_h0_kernel(const float* __restrict__ x,
                                const int*   __restrict__ y,
                                const int*   __restrict__ ind_map,
                                const float* __restrict__ skW,
                                const float* __restrict__ skb,
                                const float* __restrict__ muQ,
                                const float* __restrict__ sgQ)
{
    const int r = blockIdx.x;
    const int t = r / BS_;
    const int b = r - t * BS_;
    const int tid = threadIdx.x;

    __shared__ float xrow[NJF_];
    if (tid < NJF_) xrow[tid] = x[(size_t)b * NJF_ * T_ + tid * T_ + t];
    __syncthreads();

    const int a   = ind_map[t * BS_ + b];
    const int cls = y[b * A_ + a];
    const int start = (t == 0) ? 0 : (t + 2);

    const float div = expf(-(logf(10000.0f) / (float)LATENT_) * (float)(tid & ~1));
    const bool  odd = (tid & 1);

    float base0 = muQ[cls * LATENT_ + tid];
    float base1 = sgQ[cls * LATENT_ + tid];
    float acc = skb[tid];
    #pragma unroll 5
    for (int jf = 0; jf < NJF_; jf++) acc += xrow[jf] * skW[jf * LATENT_ + tid];

    const size_t base = (size_t)r * DM_;
    float v0, v1, v2;
    { float ang = (float)(start + 0) * div; v0 = base0 + (odd ? cosf(ang) : sinf(ang)); }
    { float ang = (float)(start + 1) * div; v1 = base1 + (odd ? cosf(ang) : sinf(ang)); }
    { float ang = (float)(start + 2) * div; v2 = acc   + (odd ? cosf(ang) : sinf(ang)); }

    g_h[base + tid]             = v0;
    g_h[base + tid + LATENT_]   = v1;
    g_h[base + tid + 2*LATENT_] = v2;
    split_store(v0, s_h_hi, s_h_lo, base + tid);
    split_store(v1, s_h_hi, s_h_lo, base + tid + LATENT_);
    split_store(v2, s_h_hi, s_h_lo, base + tid + 2*LATENT_);
}

// ---------------------------------------------------------------------------
// bf16 2-term split tensor-core GEMM (m16n8k16 + ldmatrix), cp.async pipeline.
// CTA tile 32x64, BK=32, 8 warps: 2(m) x 2(n) x 2(k-split).
// ---------------------------------------------------------------------------
#define CTM 32
#define CTN 64
#define CTK 32
#define LDA_ 40
#define LDB_ 72

__device__ __forceinline__ void gemm_bf16_core(
    const bf16* __restrict__ Ahi, const bf16* __restrict__ Alo,
    const bf16* __restrict__ Bhi, const bf16* __restrict__ Blo,
    const float* __restrict__ bias,
    float* Cf32, bf16* Shi, bf16* Slo,
    int N, int K, int rowBase, int colBase, int act, int outmode)
{
    __shared__ __align__(16) bf16 sA[2][2][CTM * LDA_];
    __shared__ __align__(16) bf16 sB[2][2][CTK * LDB_];
    __shared__ float red[2048];

    const int tid  = threadIdx.x;
    const int lane = tid & 31;
    const int wid  = tid >> 5;
    const int warp_m = wid & 1;
    const int warp_n = (wid >> 1) & 1;
    const int warp_k = wid >> 2;

    const int matA = tid >> 7;
    const int arem = tid & 127;
    const int ar = arem >> 2, ac = arem & 3;
    const int br = tid >> 3,  bc = tid & 7;

    const bf16* Asel = matA ? Alo : Ahi;
    const bf16* Agm  = Asel + (size_t)(rowBase + ar) * K + ac * 8;
    const bf16* Bgm_hi = Bhi + (size_t)br * N + colBase + bc * 8;
    const bf16* Bgm_lo = Blo + (size_t)br * N + colBase + bc * 8;

    const uint32_t adst[2] = { smem_u32(&sA[0][matA][ar * LDA_ + ac * 8]),
                               smem_u32(&sA[1][matA][ar * LDA_ + ac * 8]) };
    const uint32_t bhdst[2] = { smem_u32(&sB[0][0][br * LDB_ + bc * 8]),
                                smem_u32(&sB[1][0][br * LDB_ + bc * 8]) };
    const uint32_t bldst[2] = { smem_u32(&sB[0][1][br * LDB_ + bc * 8]),
                                smem_u32(&sB[1][1][br * LDB_ + bc * 8]) };

    const int aoff  = (warp_m * 16 + (lane & 15)) * LDA_ + warp_k * 16 + (lane >> 4) * 8;
    const int boff0 = (warp_k * 16 + (lane & 15)) * LDB_ + warp_n * 32 + (lane >> 4) * 8;
    const int boff1 = boff0 + 16;

    float4 acc[4] = {{0,0,0,0},{0,0,0,0},{0,0,0,0},{0,0,0,0}};

    const int KT = K / CTK;

    // preload tile 0 (async)
    cp16(adst[0], Agm);
    cp16(bhdst[0], Bgm_hi);
    cp16(bldst[0], Bgm_lo);
    CP_COMMIT();
    CP_WAIT0();
    __syncthreads();

    int buf = 0;
    for (int kt = 0; kt < KT; kt++) {
        const bool more = (kt + 1 < KT);
        if (more) {
            const int nb = buf ^ 1;
            cp16(adst[nb], Agm + (kt + 1) * CTK);
            cp16(bhdst[nb], Bgm_hi + (size_t)(kt + 1) * CTK * N);
            cp16(bldst[nb], Bgm_lo + (size_t)(kt + 1) * CTK * N);
            CP_COMMIT();
        }

        uint32_t ah[4], al[4], bh0[4], bh1[4], bl0[4], bl1[4];
        ldm_x4  (ah,  smem_u32(&sA[buf][0][aoff]));
        ldm_x4  (al,  smem_u32(&sA[buf][1][aoff]));
        ldm_x4_t(bh0, smem_u32(&sB[buf][0][boff0]));
        ldm_x4_t(bh1, smem_u32(&sB[buf][0][boff1]));
        ldm_x4_t(bl0, smem_u32(&sB[buf][1][boff0]));
        ldm_x4_t(bl1, smem_u32(&sB[buf][1][boff1]));

        mma_bf16(acc[0], ah, bh0[0], bh0[1]);
        mma_bf16(acc[0], ah, bl0[0], bl0[1]);
        mma_bf16(acc[0], al, bh0[0], bh0[1]);

        mma_bf16(acc[1], ah, bh0[2], bh0[3]);
        mma_bf16(acc[1], ah, bl0[2], bl0[3]);
        mma_bf16(acc[1], al, bh0[2], bh0[3]);

        mma_bf16(acc[2], ah, bh1[0], bh1[1]);
        mma_bf16(acc[2], ah, bl1[0], bl1[1]);
        mma_bf16(acc[2], al, bh1[0], bh1[1]);

        mma_bf16(acc[3], ah, bh1[2], bh1[3]);
        mma_bf16(acc[3], ah, bl1[2], bl1[3]);
        mma_bf16(acc[3], al, bh1[2], bh1[3]);

        if (more) CP_WAIT0();
        __syncthreads();
        buf ^= 1;
    }

    float* af = reinterpret_cast<float*>(acc);
    if (warp_k == 1) {
        int base = (wid - 4) * 32 + lane;
        #pragma unroll
        for (int j = 0; j < 16; j++) red[j * 128 + base] = af[j];
    }
    __syncthreads();
    if (warp_k == 0) {
        int base = wid * 32 + lane;
        #pragma unroll
        for (int j = 0; j < 16; j++) af[j] += red[j * 128 + base];

        const int row0 = rowBase + warp_m * 16 + (lane >> 2);
        #pragma unroll
        for (int nt = 0; nt < 4; nt++) {
            const int col = colBase + warp_n * 32 + nt * 8 + 2 * (lane & 3);
            float2 bb = *(const float2*)(bias + col);
            float v00 = acc[nt].x + bb.x, v01 = acc[nt].y + bb.y;
            float v10 = acc[nt].z + bb.x, v11 = acc[nt].w + bb.y;
            if (act == 1) {
                v00 = (v00 > 0.f) ? (v00 + 1.f) : expf(v00);
                v01 = (v01 > 0.f) ? (v01 + 1.f) : expf(v01);
                v10 = (v10 > 0.f) ? (v10 + 1.f) : expf(v10);
                v11 = (v11 > 0.f) ? (v11 + 1.f) : expf(v11);
            } else if (act == 2) {
                v00 = fmaxf(v00, 0.f); v01 = fmaxf(v01, 0.f);
                v10 = fmaxf(v10, 0.f); v11 = fmaxf(v11, 0.f);
            }
            if (outmode & 1) {
                *(float2*)(Cf32 + (size_t)row0 * N + col)       = make_float2(v00, v01);
                *(float2*)(Cf32 + (size_t)(row0 + 8) * N + col) = make_float2(v10, v11);
            }
            if (outmode & 2) {
                split_store(v00, Shi, Slo, (size_t)row0 * N + col);
                split_store(v01, Shi, Slo, (size_t)row0 * N + col + 1);
                split_store(v10, Shi, Slo, (size_t)(row0 + 8) * N + col);
                split_store(v11, Shi, Slo, (size_t)(row0 + 8) * N + col + 1);
            }
        }
    }
}

__global__ void __launch_bounds__(256) gemm_bf16_kernel(
    int a_code, size_t w_off, const float* __restrict__ bias,
    int N, int K, int act, int outmode, int c_code, int s_code)
{
    float* Cf32 = (outmode & 1) ? scratch(c_code) : nullptr;
    bf16* Shi = (outmode & 2) ? split_hi_w(s_code) : nullptr;
    bf16* Slo = (outmode & 2) ? split_lo_w(s_code) : nullptr;
    gemm_bf16_core(split_hi(a_code), split_lo(a_code),
                   s_W_hi + w_off, s_W_lo + w_off, bias,
                   Cf32, Shi, Slo, N, K,
                   blockIdx.y * CTM, blockIdx.x * CTN, act, outmode);
}

__global__ void __launch_bounds__(256) gemm_qkv_bf16_kernel(
    size_t offq, size_t offk, size_t offv,
    const float* __restrict__ bq,
    const float* __restrict__ bk,
    const float* __restrict__ bv)
{
    const int gcol = blockIdx.x * CTN;
    const int mat  = gcol / DM_;
    const int colBase = gcol - mat * DM_;
    size_t w_off      = (mat == 0) ? offq : (mat == 1) ? offk : offv;
    const float* bias = (mat == 0) ? bq   : (mat == 1) ? bk   : bv;
    bf16* shi         = (mat == 0) ? s_q_hi : (mat == 1) ? s_k_hi : s_v_hi;
    bf16* slo         = (mat == 0) ? s_q_lo : (mat == 1) ? s_k_lo : s_v_lo;
    const int act     = (mat < 2) ? 1 : 0;
    gemm_bf16_core(s_h_hi, s_h_lo, s_W_hi + w_off, s_W_lo + w_off, bias,
                   nullptr, shi, slo, DM_, DM_,
                   blockIdx.y * CTM, colBase, act, 2);
}

// ---------------------------------------------------------------------------
// Tensor-core causal linear attention, query-chunked + cp.async pipeline.
// Grid (5 mchunks, 32 bh), 256 threads / 8 warps.
// ---------------------------------------------------------------------------
#define SLD 88
#define QP  200
#define KP  40

__device__ __forceinline__ void split2smem(float v, bf16* hi, bf16* lo, int idx)
{
    bf16 h = __float2bfloat16_rn(v);
    hi[idx] = h;
    lo[idx] = __float2bfloat16_rn(v - __bfloat162float(h));
}

__global__ void attn_mma_kernel()
{
    __shared__ __align__(16) bf16 apool[19200];      // K/V dbl-buf [0,12800) + Q [12800,19200)
    __shared__ __align__(16) bf16 sSh[16 * SLD];
    __shared__ __align__(16) bf16 sSl[16 * SLD];
    __shared__ float inv_s[16];

    const int mc = blockIdx.x;
    const int bh = blockIdx.y;
    const int b = bh >> 2, h = bh & 3;
    const int t0 = mc * 16;
    const int W  = (mc + 1) * 16;
    const int tid = threadIdx.x, lane = tid & 31, wid = tid >> 5;
    const int g = lane >> 2, tq = lane & 3;

    const size_t rowB = (size_t)b * DM_ + h * DH_;

    float4 accA[2] = {{0,0,0,0},{0,0,0,0}};

    // prologue: Q resident + K chunk 0, all via cp.async
    for (int i = tid; i < 768; i += 256) {
        int p = i / 384, rem = i - p * 384;
        int row = rem / 24, c8 = rem - row * 24;
        const bf16* src = p ? s_q_lo : s_q_hi;
        cp16(smem_u32(&apool[12800 + p * 3200 + row * QP + c8 * 8]),
             &src[(size_t)(t0 + row) * BS_ * DM_ + rowB + c8 * 8]);
    }
    {
        const int nld = W * 8;
        for (int i = tid; i < nld; i += 256) {
            int p = i / (W * 4), rem = i - p * (W * 4);
            int row = rem >> 2, c4 = rem & 3;
            const bf16* src = p ? s_k_lo : s_k_hi;
            cp16(smem_u32(&apool[p * 3200 + row * KP + c4 * 8]),
                 &src[(size_t)row * BS_ * DM_ + rowB + c4 * 8]);
        }
    }
    CP_COMMIT();
    CP_WAIT0();
    __syncthreads();

    int buf = 0;
    for (int kc = 0; kc < 6; kc++) {
        if (kc < 5) {   // issue next K chunk BEFORE the MMAs (true overlap)
            const int nld = W * 8;
            const int cbase = (kc + 1) * 32;
            for (int i = tid; i < nld; i += 256) {
                int p = i / (W * 4), rem = i - p * (W * 4);
                int row = rem >> 2, c4 = rem & 3;
                const bf16* src = p ? s_k_lo : s_k_hi;
                cp16(smem_u32(&apool[((buf ^ 1) * 2 + p) * 3200 + row * KP + c4 * 8]),
                     &src[(size_t)row * BS_ * DM_ + rowB + cbase + c4 * 8]);
            }
            CP_COMMIT();
        }
        if (wid <= mc) {
            #pragma unroll
            for (int x = 0; x < 2; x++) {
                uint32_t qh[4], ql[4], kh[4], kl[4];
                int qoff = (lane & 15) * QP + kc * 32 + x * 16 + ((lane >> 4) << 3);
                int koff = (wid * 16 + (lane & 15)) * KP + x * 16 + ((lane >> 4) << 3);
                ldm_x4(qh, smem_u32(&apool[12800 + qoff]));
                ldm_x4(ql, smem_u32(&apool[16000 + qoff]));
                ldm_x4(kh, smem_u32(&apool[(buf * 2) * 3200 + koff]));
                ldm_x4(kl, smem_u32(&apool[(buf * 2 + 1) * 3200 + koff]));
                mma_bf16(accA[0], qh, kh[0], kh[2]);
                mma_bf16(accA[0], qh, kl[0], kl[2]);
                mma_bf16(accA[0], ql, kh[0], kh[2]);
                mma_bf16(accA[1], qh, kh[1], kh[3]);
                mma_bf16(accA[1], qh, kl[1], kl[3]);
                mma_bf16(accA[1], ql, kh[1], kh[3]);
            }
        }
        if (kc < 5) CP_WAIT0();
        __syncthreads();
        buf ^= 1;
    }

    // masked split store of S chunk (warp w -> cols [16w,16w+16))
    if (wid <= mc) {
        int r0 = g, r1 = g + 8;
        #pragma unroll
        for (int n8 = 0; n8 < 2; n8++) {
            int c = wid * 16 + n8 * 8 + 2 * tq;
            float4 a = accA[n8];
            split2smem((c     <= t0 + r0) ? a.x : 0.f, sSh, sSl, r0 * SLD + c);
            split2smem((c + 1 <= t0 + r0) ? a.y : 0.f, sSh, sSl, r0 * SLD + c + 1);
            split2smem((c     <= t0 + r1) ? a.z : 0.f, sSh, sSl, r1 * SLD + c);
            split2smem((c + 1 <= t0 + r1) ? a.w : 0.f, sSh, sSl, r1 * SLD + c + 1);
        }
    }
    __syncthreads();

    // issue V chunk 0 async, then rowsum overlaps the copy
    for (int i = tid; i < 768; i += 256) {
        int p = i / 384, rem = i - p * 384;
        int row = rem / 24, c8 = rem - row * 24;
        const bf16* src = p ? s_v_lo : s_v_hi;
        cp16(smem_u32(&apool[p * 3200 + row * QP + c8 * 8]),
             &src[(size_t)row * BS_ * DM_ + rowB + c8 * 8]);
    }
    CP_COMMIT();
    if (tid < 16) {
        float s = 0.0f;
        for (int c = 0; c < W; c++)
            s += __bfloat162float(sSh[tid * SLD + c]) + __bfloat162float(sSl[tid * SLD + c]);
        inv_s[tid] = 1.0f / (s + EPS_ATT);
    }
    CP_WAIT0();
    __syncthreads();

    float4 accC[2][2];
    #pragma unroll
    for (int j = 0; j < 2; j++) { accC[j][0] = make_float4(0,0,0,0); accC[j][1] = make_float4(0,0,0,0); }

    buf = 0;
    for (int vc = 0; vc <= mc; vc++) {
        if (vc < mc) {   // issue next V chunk before the MMAs
            const int rbase = (vc + 1) * 16;
            for (int i = tid; i < 768; i += 256) {
                int p = i / 384, rem = i - p * 384;
                int row = rem / 24, c8 = rem - row * 24;
                const bf16* src = p ? s_v_lo : s_v_hi;
                cp16(smem_u32(&apool[((buf ^ 1) * 2 + p) * 3200 + row * QP + c8 * 8]),
                     &src[(size_t)(rbase + row) * BS_ * DM_ + rowB + c8 * 8]);
            }
            CP_COMMIT();
        }

        uint32_t sh[4], sl[4];
        int aoff = (lane & 15) * SLD + vc * 16 + ((lane >> 4) << 3);
        ldm_x4(sh, smem_u32(&sSh[aoff]));
        ldm_x4(sl, smem_u32(&sSl[aoff]));

        #pragma unroll
        for (int j = 0; j < 2; j++) {
            int ni = wid + 8 * j;
            if (ni < 12) {
                uint32_t vh[4], vl[4];
                int boff = (lane & 15) * QP + ni * 16 + ((lane >> 4) << 3);
                ldm_x4_t(vh, smem_u32(&apool[(buf * 2) * 3200 + boff]));
                ldm_x4_t(vl, smem_u32(&apool[(buf * 2 + 1) * 3200 + boff]));
                mma_bf16(accC[j][0], sh, vh[0], vh[1]);
                mma_bf16(accC[j][0], sh, vl[0], vl[1]);
                mma_bf16(accC[j][0], sl, vh[0], vh[1]);
                mma_bf16(accC[j][1], sh, vh[2], vh[3]);
                mma_bf16(accC[j][1], sh, vl[2], vl[3]);
                mma_bf16(accC[j][1], sl, vh[2], vh[3]);
            }
        }

        if (vc < mc) CP_WAIT0();
        __syncthreads();
        buf ^= 1;
    }

    {
        int r0 = g, r1 = g + 8;
        float i0 = inv_s[r0], i1 = inv_s[r1];
        #pragma unroll
        for (int j = 0; j < 2; j++) {
            int ni = wid + 8 * j;
            if (ni < 12) {
                #pragma unroll
                for (int n8 = 0; n8 < 2; n8++) {
                    int d = ni * 16 + n8 * 8 + 2 * tq;
                    float4 a = accC[j][n8];
                    size_t o0 = (size_t)(t0 + r0) * BS_ * DM_ + rowB + d;
                    size_t o1 = (size_t)(t0 + r1) * BS_ * DM_ + rowB + d;
                    split_store(a.x * i0, s_att_hi, s_att_lo, o0);
                    split_store(a.y * i0, s_att_hi, s_att_lo, o0 + 1);
                    split_store(a.z * i1, s_att_hi, s_att_lo, o1);
                    split_store(a.w * i1, s_att_hi, s_att_lo, o1 + 1);
                }
            }
        }
    }
}

// ---------------------------------------------------------------------------
// LayerNorm
// ---------------------------------------------------------------------------
__device__ __forceinline__ float block_sum_256(float val)
{
    __shared__ float sh[8];
    const int lane = threadIdx.x & 31;
    const int w    = threadIdx.x >> 5;
    #pragma unroll
    for (int o = 16; o > 0; o >>= 1) val += __shfl_down_sync(0xffffffffu, val, o);
    if (lane == 0) sh[w] = val;
    __syncthreads();
    if (w == 0) {
        float r = (lane < 8) ? sh[lane] : 0.0f;
        #pragma unroll
        for (int o = 4; o > 0; o >>= 1) r += __shfl_down_sync(0xffffffffu, r, o);
        if (lane == 0) sh[0] = r;
    }
    __syncthreads();
    float res = sh[0];
    __syncthreads();
    return res;
}

__global__ void ln_residual_kernel(int x_code, int y_code,
                                   const float* __restrict__ g, const float* __restrict__ bt,
                                   int out_code, int s_code)
{
    const float* x  = scratch(x_code);
    const float* yv = scratch(y_code);
    float* out      = scratch(out_code);
    bf16* shi = split_hi_w(s_code);
    bf16* slo = split_lo_w(s_code);

    const int row = blockIdx.x;
    const int tid = threadIdx.x;
    const size_t base = (size_t)row * DM_;

    float v0 = x[base + tid]       + yv[base + tid];
    float v1 = x[base + tid + 256] + yv[base + tid + 256];
    float v2 = x[base + tid + 512] + yv[base + tid + 512];

    float mean = block_sum_256(v0 + v1 + v2) * (1.0f / (float)DM_);
    float d0 = v0 - mean, d1 = v1 - mean, d2 = v2 - mean;
    float var = block_sum_256(d0*d0 + d1*d1 + d2*d2) * (1.0f / (float)DM_);
    float rstd = rsqrtf(var + EPS_LN);

    float o0 = d0 * rstd * g[tid]       + bt[tid];
    float o1 = d1 * rstd * g[tid + 256] + bt[tid + 256];
    float o2 = d2 * rstd * g[tid + 512] + bt[tid + 512];

    out[base + tid]       = o0;
    out[base + tid + 256] = o1;
    out[base + tid + 512] = o2;
    split_store(o0, shi, slo, base + tid);
    split_store(o1, shi, slo, base + tid + 256);
    split_store(o2, shi, slo, base + tid + 512);
}

// ---------------------------------------------------------------------------
// Final gather + LN
// ---------------------------------------------------------------------------
__global__ void gather_kernel(const int* __restrict__ act_ts,
                              const float* __restrict__ g, const float* __restrict__ bt,
                              float* __restrict__ out)
{
    const int ba = blockIdx.x;
    const int b  = ba / A_;
    int t = act_ts[ba] - 1;
    if (t < 0) t = 0;
    const int row = t * BS_ + b;
    const int tid = threadIdx.x;
    const size_t base = (size_t)row * DM_;

    float v0 = g_h[base + tid];
    float v1 = g_h[base + tid + 256];
    float v2 = g_h[base + tid + 512];

    float mean = block_sum_256(v0 + v1 + v2) * (1.0f / (float)DM_);
    float d0 = v0 - mean, d1 = v1 - mean, d2 = v2 - mean;
    float var = block_sum_256(d0*d0 + d1*d1 + d2*d2) * (1.0f / (float)DM_);
    float rstd = rsqrtf(var + EPS_LN);

    out[(size_t)ba * LATENT_ + tid]                      = d0 * rstd * g[tid]       + bt[tid];
    out[(size_t)BS_ * A_ * LATENT_ + ba * LATENT_ + tid] = d1 * rstd * g[tid + 256] + bt[tid + 256];
}

// ---------------------------------------------------------------------------
// Host orchestration: kernel launches ONLY
// ---------------------------------------------------------------------------
extern "C" void kernel_launch(void* const* d_in, const int* in_sizes, int n_in,
                              void* d_out, int out_size)
{
    const float* x    = (const float*)d_in[0];
    const int*   y    = (const int*)  d_in[1];
    const int*   ind  = (const int*)  d_in[2];
    const int*   ats  = (const int*)  d_in[3];
    const float* skW  = (const float*)d_in[4];
    const float* skb  = (const float*)d_in[5];
    const float* muQ  = (const float*)d_in[6];
    const float* sgQ  = (const float*)d_in[7];
    const float* Wq   = (const float*)d_in[8];
    const float* bq   = (const float*)d_in[9];
    const float* Wk   = (const float*)d_in[10];
    const float* bk   = (const float*)d_in[11];
    const float* Wv   = (const float*)d_in[12];
    const float* bv   = (const float*)d_in[13];
    const float* Wo   = (const float*)d_in[14];
    const float* bo   = (const float*)d_in[15];
    const float* W1   = (const float*)d_in[16];
    const float* b1   = (const float*)d_in[17];
    const float* W2   = (const float*)d_in[18];
    const float* b2   = (const float*)d_in[19];
    const float* l1g  = (const float*)d_in[20];
    const float* l1b  = (const float*)d_in[21];
    const float* l2g  = (const float*)d_in[22];
    const float* l2b  = (const float*)d_in[23];
    const float* lfg  = (const float*)d_in[24];
    const float* lfb  = (const float*)d_in[25];
    float* out = (float*)d_out;

    split_weights_kernel<<<(unsigned)((TOTALW / 4 + 255) / 256), 256>>>(Wq, Wk, Wv, Wo, W1, W2);
    build_h0_kernel<<<ROWS_, 256>>>(x, y, ind, skW, skb, muQ, sgQ);

    const dim3 gQKV(3 * DM_ / CTN, ROWS_ / CTM);   // 36 x 20 = 720
    const dim3 g768(DM_ / CTN, ROWS_ / CTM);       // 12 x 20 = 240
    const dim3 g1024(FF_ / CTN, ROWS_ / CTM);      // 16 x 20 = 320
    const dim3 gAttn(5, BS_ * H_);                 // 160 blocks

    const size_t szAttL = (size_t)DM_ * DM_;
    const size_t szFFL  = (size_t)DM_ * FF_;

    for (int l = 0; l < L_; l++) {
        gemm_qkv_bf16_kernel<<<gQKV, 256>>>(OFF_WQ + l * szAttL,
                                            OFF_WK + l * szAttL,
                                            OFF_WV + l * szAttL,
                                            bq + l * DM_, bk + l * DM_, bv + l * DM_);
        attn_mma_kernel<<<gAttn, 256>>>();
        gemm_bf16_kernel<<<g768, 256>>>(SPL_ATT, OFF_WO + l * szAttL, bo + l * DM_,
                                        DM_, DM_, 0, 1, BUF_Q, 0);
        ln_residual_kernel<<<ROWS_, 256>>>(BUF_H, BUF_Q, l1g + l * DM_, l1b + l * DM_,
                                           BUF_H1, SPL_H1);
        gemm_bf16_kernel<<<g1024, 256>>>(SPL_H1, OFF_W1 + l * szFFL, b1 + l * FF_,
                                         FF_, DM_, 2, 2, 0, SPL_FF);
        gemm_bf16_kernel<<<g768, 256>>>(SPL_FF, OFF_W2 + l * szFFL, b2 + l * DM_,
                                        DM_, FF_, 0, 1, BUF_Q, 0);
        ln_residual_kernel<<<ROWS_, 256>>>(BUF_H1, BUF_Q, l2g + l * DM_, l2b + l * DM_,
                                           BUF_H, SPL_H);
    }

    gather_kernel<<<BS_ * A_, 256>>>(ats, lfg, lfb, out);
}